// round 14
// baseline (speedup 1.0000x reference)
#include <cuda_runtime.h>
#include <cuda_bf16.h>

// Fused GNN: 2 threads/element, f32x2 packed math.
// R14: WARP-LOCAL SMEM TRANSPOSITION. The per-thread 80/160B-stride LDG.128s
// cost ~20-40 L1 wavefronts each (the real binder, L1=67%). Each warp now
// loads its 32 slots' x/z/y with consecutive lane addresses (4 wf per LDG),
// stages through shared, reads own rows via conflict-free LDS; output staged
// back and stored cooperatively. Global wavefronts/warp: ~700 -> ~100.

typedef unsigned long long u64;

static __device__ __forceinline__ u64 pk2(float a, float b) {
    u64 r; asm("mov.b64 %0, {%1, %2};" : "=l"(r) : "f"(a), "f"(b)); return r;
}
static __device__ __forceinline__ void upk2(u64 v, float& a, float& b) {
    asm("mov.b64 {%0, %1}, %2;" : "=f"(a), "=f"(b) : "l"(v));
}
static __device__ __forceinline__ u64 fma2(u64 a, u64 b, u64 c) {
    u64 d; asm("fma.rn.f32x2 %0, %1, %2, %3;" : "=l"(d) : "l"(a), "l"(b), "l"(c)); return d;
}
static __device__ __forceinline__ u64 add2(u64 a, u64 b) {
    u64 d; asm("add.rn.f32x2 %0, %1, %2;" : "=l"(d) : "l"(a), "l"(b)); return d;
}

__global__ void __launch_bounds__(128, 6) gnn_fused_kernel(
    const float* __restrict__ x,
    const float* __restrict__ z,
    const float* __restrict__ y,
    const float* __restrict__ enc_rel_w,
    const float* __restrict__ enc_rel_b,
    const float* __restrict__ enc_root_w,
    const float* __restrict__ pred_rel_w,
    const float* __restrict__ pred_rel_b,
    const float* __restrict__ pred_root_w,
    const float* __restrict__ dec_rel_w,
    const float* __restrict__ dec_rel_b,
    const float* __restrict__ dec_root_w,
    float* __restrict__ out,
    int NT)   // NT = 2*B element-half slots
{
    __shared__ __align__(16) u64 sWRt2[32];  // [g*4+p]: enc_root_w^T packed over f
    __shared__ __align__(16) u64 sW2[64];    // [(fp*8+g)*2 + {0:wa,1:wb}]
    __shared__ __align__(16) u64 sEW2[4], sEB2[4], sPB2[4];
    __shared__ float sDW[8];
    __shared__ float sDB, sDR;
    __shared__ __align__(16) float4 bufA[4][160];   // per-warp: x -> y -> out (80B/thread)
    __shared__ __align__(16) float4 bufZ[4][352];   // per-warp: z, 11-f4 padded rows (176B/thread)

    const int tid = threadIdx.x;
    if (tid < 32) {
        {
            const int g = tid >> 2, p = tid & 3;
            sWRt2[g * 4 + p] = pk2(enc_root_w[(2*p)*8 + g], enc_root_w[(2*p + 1)*8 + g]);
        }
        {
            const int fp = tid >> 3, g = tid & 7;
            const float w = expf(-1.0f / 9.0f);
            float pr0 = pred_rel_w[(2*fp)*8 + g],   pr1 = pred_rel_w[(2*fp + 1)*8 + g];
            float po0 = pred_root_w[(2*fp)*8 + g],  po1 = pred_root_w[(2*fp + 1)*8 + g];
            sW2[(fp*8 + g)*2 + 0] = pk2(pr0 + po0, pr1 + po1);   // wa
            sW2[(fp*8 + g)*2 + 1] = pk2(w * pr0, w * pr1);       // wb
        }
    }
    if (tid < 4) {
        sEW2[tid] = pk2(enc_rel_w[2*tid], enc_rel_w[2*tid + 1]);
        sEB2[tid] = pk2(enc_rel_b[2*tid], enc_rel_b[2*tid + 1]);
        sPB2[tid] = pk2(pred_rel_b[2*tid], pred_rel_b[2*tid + 1]);
    }
    if (tid < 8) sDW[tid] = dec_rel_w[tid];
    if (tid == 0) { sDB = dec_rel_b[0]; sDR = dec_root_w[0]; }
    __syncthreads();

    const int w    = tid >> 5;                       // warp in block
    const int lane = tid & 31;
    const int wg   = blockIdx.x * 4 + w;             // global warp id
    const int slot = wg * 32 + lane;                 // element-half slot
    const bool active = (slot < NT);

    const int xcnt = NT * 5;                         // total float4 in x / y / out
    const int zcnt = NT * 10;
    const int xbase = wg * 160;                      // warp's float4 base in x/y/out
    const int zbase = wg * 320;

    const float4* x4 = reinterpret_cast<const float4*>(x);
    const float4* z4 = reinterpret_cast<const float4*>(z);
    const float4* y4 = reinterpret_cast<const float4*>(y);
    float4*       o4 = reinterpret_cast<float4*>(out);

    // ---------- cooperative stage: x (5 rounds) + z (10 rounds), coalesced ----------
    {
        float4 xv[5];
        #pragma unroll
        for (int r = 0; r < 5; r++) {
            int gi = xbase + r*32 + lane;
            xv[r] = x4[gi < xcnt ? gi : (xcnt - 1)];
        }
        float4 zv[10];
        #pragma unroll
        for (int r = 0; r < 10; r++) {
            int gi = zbase + r*32 + lane;
            zv[r] = z4[gi < zcnt ? gi : (zcnt - 1)];
        }
        #pragma unroll
        for (int r = 0; r < 5; r++) bufA[w][r*32 + lane] = xv[r];
        #pragma unroll
        for (int r = 0; r < 10; r++) {
            int idx = r*32 + lane;          // warp-local float4 index into z block
            int t10 = idx / 10;             // owning thread
            int j   = idx - t10 * 10;       // slot within row
            bufZ[w][t10*11 + j] = zv[r];
        }
    }
    __syncwarp();

    // ---------- read own x row (conflict-free: banks lane*20 mod 32 distinct/phase) ----------
    float4 c[5];
    #pragma unroll
    for (int i = 0; i < 5; i++) c[i] = bufA[w][lane*5 + i];
    __syncwarp();   // bufA free for y

    // ---------- s[5] ----------
    float s[5];
    {
        float m1 = __shfl_xor_sync(0xFFFFFFFFu, c[4].y, 1);
        float m2 = __shfl_xor_sync(0xFFFFFFFFu, c[4].z, 1);
        float m3 = __shfl_xor_sync(0xFFFFFFFFu, c[4].w, 1);
        s[0] = ((m1 + m2) + (m3 + c[0].x)) + (c[0].y + c[0].z);
        #pragma unroll
        for (int k = 1; k < 5; k++) {
            float a0 = c[k-1].y + c[k-1].z;
            float a1 = c[k-1].w + c[k].x;
            float a2 = c[k].y + c[k].z;
            s[k] = (a0 + a1) + a2;
        }
    }

    // ---------- stage y into bufA (consumed after predictor) ----------
    #pragma unroll
    for (int r = 0; r < 5; r++) {
        int gi = xbase + r*32 + lane;
        bufA[w][r*32 + lane] = y4[gi < xcnt ? gi : (xcnt - 1)];
    }

    // ---------- encoder, k-outer (z from smem, conflict-free) ----------
    float z1[40];
    {
        const ulonglong2* EW = reinterpret_cast<const ulonglong2*>(sEW2);
        const ulonglong2* EB = reinterpret_cast<const ulonglong2*>(sEB2);
        const ulonglong2* WR = reinterpret_cast<const ulonglong2*>(sWRt2);
        ulonglong2 ew01 = EW[0], ew23 = EW[1];
        ulonglong2 eb01 = EB[0], eb23 = EB[1];
        #pragma unroll
        for (int k = 0; k < 5; k++) {
            float4 za = bufZ[w][lane*11 + 2*k];
            float4 zb = bufZ[w][lane*11 + 2*k + 1];
            const float zv[8] = {za.x, za.y, za.z, za.w, zb.x, zb.y, zb.z, zb.w};
            u64 sk = pk2(s[k], s[k]);
            u64 A0 = fma2(sk, ew01.x, eb01.x);
            u64 A1 = fma2(sk, ew01.y, eb01.y);
            u64 A2 = fma2(sk, ew23.x, eb23.x);
            u64 A3 = fma2(sk, ew23.y, eb23.y);
            #pragma unroll
            for (int g = 0; g < 8; g++) {
                ulonglong2 w01 = WR[g*2];
                ulonglong2 w23 = WR[g*2 + 1];
                u64 zg = pk2(zv[g], zv[g]);
                A0 = fma2(zg, w01.x, A0);
                A1 = fma2(zg, w01.y, A1);
                A2 = fma2(zg, w23.x, A2);
                A3 = fma2(zg, w23.y, A3);
            }
            float a, b;
            upk2(A0, a, b); z1[k*8+0] = fmaxf(a, 0.f); z1[k*8+1] = fmaxf(b, 0.f);
            upk2(A1, a, b); z1[k*8+2] = fmaxf(a, 0.f); z1[k*8+3] = fmaxf(b, 0.f);
            upk2(A2, a, b); z1[k*8+4] = fmaxf(a, 0.f); z1[k*8+5] = fmaxf(b, 0.f);
            upk2(A3, a, b); z1[k*8+6] = fmaxf(a, 0.f); z1[k*8+7] = fmaxf(b, 0.f);
        }
    }

    // ---------- predictor + decoder-rel fused ----------
    float t[5] = {0.f, 0.f, 0.f, 0.f, 0.f};
    {
        const ulonglong2* W = reinterpret_cast<const ulonglong2*>(sW2);
        #pragma unroll
        for (int fp = 0; fp < 4; fp++) {
            u64 pb = sPB2[fp];
            u64 u2[5], v2[5];
            #pragma unroll
            for (int k = 0; k < 5; k++) { u2[k] = pb; v2[k] = 0ULL; }
            #pragma unroll
            for (int g = 0; g < 8; g++) {
                ulonglong2 wv = W[fp*8 + g];   // {wa, wb}
                #pragma unroll
                for (int k = 0; k < 5; k++) {
                    u64 zg = pk2(z1[k*8 + g], z1[k*8 + g]);
                    u2[k] = fma2(zg, wv.x, u2[k]);
                    v2[k] = fma2(zg, wv.y, v2[k]);
                }
            }
            float va, vb;
            upk2(v2[4], va, vb);
            float vma = __shfl_xor_sync(0xFFFFFFFFu, va, 1);
            float vmb = __shfl_xor_sync(0xFFFFFFFFu, vb, 1);
            u64 vm2 = pk2(vma, vmb);
            upk2(v2[0], va, vb);
            float vpa = __shfl_xor_sync(0xFFFFFFFFu, va, 1);
            float vpb = __shfl_xor_sync(0xFFFFFFFFu, vb, 1);
            u64 vp2 = pk2(vpa, vpb);

            const float dw0 = sDW[2*fp], dw1 = sDW[2*fp + 1];
            #pragma unroll
            for (int k = 0; k < 5; k++) {
                u64 nb  = add2(k == 0 ? vm2 : v2[k-1], k == 4 ? vp2 : v2[k+1]);
                u64 pre = add2(u2[k], nb);
                float p0, p1; upk2(pre, p0, p1);
                t[k] = fmaf(fmaxf(p0, 0.0f), dw0, t[k]);
                t[k] = fmaf(fmaxf(p1, 0.0f), dw1, t[k]);
            }
        }
    }

    // ---------- decoder: read y row, write out row back into bufA ----------
    float T6[6];
    #pragma unroll
    for (int k = 0; k < 5; k++) T6[k] = t[k];
    T6[5] = __shfl_xor_sync(0xFFFFFFFFu, t[0], 1);

    __syncwarp();   // y staging visible to all lanes (self rows anyway)
    const float dB = sDB, dR = sDR;
    #pragma unroll
    for (int q = 0; q < 5; q++) {
        float4 yv = bufA[w][lane*5 + q];
        float yc[4] = {yv.x, yv.y, yv.z, yv.w};
        float r[4];
        #pragma unroll
        for (int cc = 0; cc < 4; cc++) {
            const int i = 4*q + cc;
            const int lo = (i + 1) / 4;
            const int hi = (i + 3) / 4;
            float agg = T6[lo];
            if (hi != lo) agg += T6[hi];
            r[cc] = fmaf(yc[cc], dR, agg + dB);
        }
        bufA[w][lane*5 + q] = make_float4(r[0], r[1], r[2], r[3]);
    }
    __syncwarp();

    // ---------- cooperative coalesced store ----------
    #pragma unroll
    for (int r = 0; r < 5; r++) {
        int gi = xbase + r*32 + lane;
        float4 v = bufA[w][r*32 + lane];
        if (gi < xcnt) o4[gi] = v;
    }
    (void)active;
}

extern "C" void kernel_launch(void* const* d_in, const int* in_sizes, int n_in,
                              void* d_out, int out_size) {
    const float* x           = (const float*)d_in[0];
    const float* z           = (const float*)d_in[1];
    const float* y           = (const float*)d_in[2];
    const float* enc_rel_w   = (const float*)d_in[3];
    const float* enc_rel_b   = (const float*)d_in[4];
    const float* enc_root_w  = (const float*)d_in[5];
    const float* pred_rel_w  = (const float*)d_in[6];
    const float* pred_rel_b  = (const float*)d_in[7];
    const float* pred_root_w = (const float*)d_in[8];
    const float* dec_rel_w   = (const float*)d_in[9];
    const float* dec_rel_b   = (const float*)d_in[10];
    const float* dec_root_w  = (const float*)d_in[11];
    float* out = (float*)d_out;

    const int B  = in_sizes[0] / 40;
    const int NT = 2 * B;
    const int threads = 128;
    const int blocks = (NT + threads - 1) / threads;
    gnn_fused_kernel<<<blocks, threads>>>(
        x, z, y, enc_rel_w, enc_rel_b, enc_root_w,
        pred_rel_w, pred_rel_b, pred_root_w,
        dec_rel_w, dec_rel_b, dec_root_w, out, NT);
}

// round 15
// speedup vs baseline: 1.2118x; 1.2118x over previous
#include <cuda_runtime.h>
#include <cuda_bf16.h>

// Fused GNN: 2 threads/element, f32x2 packed math — R10 champion body.
// R15: 256-thread CTAs (launch_bounds(256,3): same 24 warps/SM, 80 regs fits
// the 85-reg budget) -> half the CTA count -> half the weight-staging
// prologues and CTA boundaries. Kernel body identical to R10 (74.5us).

typedef unsigned long long u64;

static __device__ __forceinline__ u64 pk2(float a, float b) {
    u64 r; asm("mov.b64 %0, {%1, %2};" : "=l"(r) : "f"(a), "f"(b)); return r;
}
static __device__ __forceinline__ void upk2(u64 v, float& a, float& b) {
    asm("mov.b64 {%0, %1}, %2;" : "=f"(a), "=f"(b) : "l"(v));
}
static __device__ __forceinline__ u64 fma2(u64 a, u64 b, u64 c) {
    u64 d; asm("fma.rn.f32x2 %0, %1, %2, %3;" : "=l"(d) : "l"(a), "l"(b), "l"(c)); return d;
}
static __device__ __forceinline__ u64 add2(u64 a, u64 b) {
    u64 d; asm("add.rn.f32x2 %0, %1, %2;" : "=l"(d) : "l"(a), "l"(b)); return d;
}

__global__ void __launch_bounds__(256, 3) gnn_fused_kernel(
    const float* __restrict__ x,
    const float* __restrict__ z,
    const float* __restrict__ y,
    const float* __restrict__ enc_rel_w,
    const float* __restrict__ enc_rel_b,
    const float* __restrict__ enc_root_w,
    const float* __restrict__ pred_rel_w,
    const float* __restrict__ pred_rel_b,
    const float* __restrict__ pred_root_w,
    const float* __restrict__ dec_rel_w,
    const float* __restrict__ dec_rel_b,
    const float* __restrict__ dec_root_w,
    float* __restrict__ out,
    int NT)   // NT = 2*B threads
{
    __shared__ __align__(16) u64 sWRt2[32];  // [g*4+p]: enc_root_w^T packed over f
    __shared__ __align__(16) u64 sW2[64];    // [(fp*8+g)*2 + {0:wa,1:wb}]
    __shared__ __align__(16) u64 sEW2[4], sEB2[4], sPB2[4];
    __shared__ float sDW[8];
    __shared__ float sDB, sDR;

    const int tid = threadIdx.x;
    if (tid < 32) {
        {
            const int g = tid >> 2, p = tid & 3;
            sWRt2[g * 4 + p] = pk2(enc_root_w[(2*p)*8 + g], enc_root_w[(2*p + 1)*8 + g]);
        }
        {
            const int fp = tid >> 3, g = tid & 7;
            const float w = expf(-1.0f / 9.0f);
            float pr0 = pred_rel_w[(2*fp)*8 + g],   pr1 = pred_rel_w[(2*fp + 1)*8 + g];
            float po0 = pred_root_w[(2*fp)*8 + g],  po1 = pred_root_w[(2*fp + 1)*8 + g];
            sW2[(fp*8 + g)*2 + 0] = pk2(pr0 + po0, pr1 + po1);   // wa
            sW2[(fp*8 + g)*2 + 1] = pk2(w * pr0, w * pr1);       // wb
        }
    }
    if (tid < 4) {
        sEW2[tid] = pk2(enc_rel_w[2*tid], enc_rel_w[2*tid + 1]);
        sEB2[tid] = pk2(enc_rel_b[2*tid], enc_rel_b[2*tid + 1]);
        sPB2[tid] = pk2(pred_rel_b[2*tid], pred_rel_b[2*tid + 1]);
    }
    if (tid < 8) sDW[tid] = dec_rel_w[tid];
    if (tid == 0) { sDB = dec_rel_b[0]; sDR = dec_root_w[0]; }
    __syncthreads();

    const int gt = blockIdx.x * blockDim.x + tid;
    if (gt >= NT) return;

    // ---------- coalesced front-batched loads (full MLP=15) ----------
    float4 c[5];
    {
        const float4* xp = reinterpret_cast<const float4*>(x) + gt * 5;
        #pragma unroll
        for (int i = 0; i < 5; i++) c[i] = xp[i];
    }
    float4 zl[10];
    {
        const float4* zp = reinterpret_cast<const float4*>(z) + gt * 10;
        #pragma unroll
        for (int i = 0; i < 10; i++) zl[i] = zp[i];
    }

    // ---------- s[5] straight from c[] ----------
    float s[5];
    {
        float m1 = __shfl_xor_sync(0xFFFFFFFFu, c[4].y, 1);
        float m2 = __shfl_xor_sync(0xFFFFFFFFu, c[4].z, 1);
        float m3 = __shfl_xor_sync(0xFFFFFFFFu, c[4].w, 1);
        s[0] = ((m1 + m2) + (m3 + c[0].x)) + (c[0].y + c[0].z);
        #pragma unroll
        for (int k = 1; k < 5; k++) {
            float a0 = c[k-1].y + c[k-1].z;
            float a1 = c[k-1].w + c[k].x;
            float a2 = c[k].y + c[k].z;
            s[k] = (a0 + a1) + a2;
        }
    }

    // ---------- encoder, k-outer: 4 packed accumulators per node ----------
    float z1[40];
    {
        const ulonglong2* EW = reinterpret_cast<const ulonglong2*>(sEW2);
        const ulonglong2* EB = reinterpret_cast<const ulonglong2*>(sEB2);
        const ulonglong2* WR = reinterpret_cast<const ulonglong2*>(sWRt2);
        ulonglong2 ew01 = EW[0], ew23 = EW[1];
        ulonglong2 eb01 = EB[0], eb23 = EB[1];
        #pragma unroll
        for (int k = 0; k < 5; k++) {
            float4 za = zl[2*k], zb = zl[2*k + 1];
            const float zv[8] = {za.x, za.y, za.z, za.w, zb.x, zb.y, zb.z, zb.w};
            u64 sk = pk2(s[k], s[k]);
            u64 A0 = fma2(sk, ew01.x, eb01.x);
            u64 A1 = fma2(sk, ew01.y, eb01.y);
            u64 A2 = fma2(sk, ew23.x, eb23.x);
            u64 A3 = fma2(sk, ew23.y, eb23.y);
            #pragma unroll
            for (int g = 0; g < 8; g++) {
                ulonglong2 w01 = WR[g*2];
                ulonglong2 w23 = WR[g*2 + 1];
                u64 zg = pk2(zv[g], zv[g]);
                A0 = fma2(zg, w01.x, A0);
                A1 = fma2(zg, w01.y, A1);
                A2 = fma2(zg, w23.x, A2);
                A3 = fma2(zg, w23.y, A3);
            }
            float a, b;
            upk2(A0, a, b); z1[k*8+0] = fmaxf(a, 0.f); z1[k*8+1] = fmaxf(b, 0.f);
            upk2(A1, a, b); z1[k*8+2] = fmaxf(a, 0.f); z1[k*8+3] = fmaxf(b, 0.f);
            upk2(A2, a, b); z1[k*8+4] = fmaxf(a, 0.f); z1[k*8+5] = fmaxf(b, 0.f);
            upk2(A3, a, b); z1[k*8+6] = fmaxf(a, 0.f); z1[k*8+7] = fmaxf(b, 0.f);
        }
    }

    // ---------- predictor + decoder-rel fused, (fp,g)-outer k-inner ----------
    float t[5] = {0.f, 0.f, 0.f, 0.f, 0.f};
    {
        const ulonglong2* W = reinterpret_cast<const ulonglong2*>(sW2);
        #pragma unroll
        for (int fp = 0; fp < 4; fp++) {
            u64 pb = sPB2[fp];
            u64 u2[5], v2[5];
            #pragma unroll
            for (int k = 0; k < 5; k++) { u2[k] = pb; v2[k] = 0ULL; }
            #pragma unroll
            for (int g = 0; g < 8; g++) {
                ulonglong2 w = W[fp*8 + g];   // {wa, wb}
                #pragma unroll
                for (int k = 0; k < 5; k++) {
                    u64 zg = pk2(z1[k*8 + g], z1[k*8 + g]);
                    u2[k] = fma2(zg, w.x, u2[k]);
                    v2[k] = fma2(zg, w.y, v2[k]);
                }
            }
            float va, vb;
            upk2(v2[4], va, vb);
            float vma = __shfl_xor_sync(0xFFFFFFFFu, va, 1);
            float vmb = __shfl_xor_sync(0xFFFFFFFFu, vb, 1);
            u64 vm2 = pk2(vma, vmb);
            upk2(v2[0], va, vb);
            float vpa = __shfl_xor_sync(0xFFFFFFFFu, va, 1);
            float vpb = __shfl_xor_sync(0xFFFFFFFFu, vb, 1);
            u64 vp2 = pk2(vpa, vpb);

            const float dw0 = sDW[2*fp], dw1 = sDW[2*fp + 1];
            #pragma unroll
            for (int k = 0; k < 5; k++) {
                u64 nb  = add2(k == 0 ? vm2 : v2[k-1], k == 4 ? vp2 : v2[k+1]);
                u64 pre = add2(u2[k], nb);
                float p0, p1; upk2(pre, p0, p1);
                t[k] = fmaf(fmaxf(p0, 0.0f), dw0, t[k]);
                t[k] = fmaf(fmaxf(p1, 0.0f), dw1, t[k]);
            }
        }
    }

    // ---------- decoder aggregation + root + output ----------
    float T6[6];
    #pragma unroll
    for (int k = 0; k < 5; k++) T6[k] = t[k];
    T6[5] = __shfl_xor_sync(0xFFFFFFFFu, t[0], 1);

    const float dB = sDB, dR = sDR;
    const float4* yp = reinterpret_cast<const float4*>(y) + gt * 5;
    float4* op = reinterpret_cast<float4*>(out) + gt * 5;
    #pragma unroll
    for (int q = 0; q < 5; q++) {
        float4 yv = yp[q];
        float yc[4] = {yv.x, yv.y, yv.z, yv.w};
        float r[4];
        #pragma unroll
        for (int cc = 0; cc < 4; cc++) {
            const int i = 4*q + cc;
            const int lo = (i + 1) / 4;
            const int hi = (i + 3) / 4;
            float agg = T6[lo];
            if (hi != lo) agg += T6[hi];
            r[cc] = fmaf(yc[cc], dR, agg + dB);
        }
        op[q] = make_float4(r[0], r[1], r[2], r[3]);
    }
}

extern "C" void kernel_launch(void* const* d_in, const int* in_sizes, int n_in,
                              void* d_out, int out_size) {
    const float* x           = (const float*)d_in[0];
    const float* z           = (const float*)d_in[1];
    const float* y           = (const float*)d_in[2];
    const float* enc_rel_w   = (const float*)d_in[3];
    const float* enc_rel_b   = (const float*)d_in[4];
    const float* enc_root_w  = (const float*)d_in[5];
    const float* pred_rel_w  = (const float*)d_in[6];
    const float* pred_rel_b  = (const float*)d_in[7];
    const float* pred_root_w = (const float*)d_in[8];
    const float* dec_rel_w   = (const float*)d_in[9];
    const float* dec_rel_b   = (const float*)d_in[10];
    const float* dec_root_w  = (const float*)d_in[11];
    float* out = (float*)d_out;

    const int B  = in_sizes[0] / 40;
    const int NT = 2 * B;
    const int threads = 256;
    const int blocks = (NT + threads - 1) / threads;
    gnn_fused_kernel<<<blocks, threads>>>(
        x, z, y, enc_rel_w, enc_rel_b, enc_root_w,
        pred_rel_w, pred_rel_b, pred_root_w,
        dec_rel_w, dec_rel_b, dec_root_w, out, NT);
}

// round 16
// speedup vs baseline: 1.2970x; 1.0703x over previous
#include <cuda_runtime.h>
#include <cuda_bf16.h>

// Fused GNN: 2 threads/element, f32x2 packed math — R10 champion body.
// R16: 64-thread CTAs. Block-size trend measured: 256 -> 79.5us, 128 -> 74.5us;
// gradient points smaller. launch_bounds(64,12) keeps 24 warps/SM @ 80 regs,
// halves the per-CTA load-burst footprint at the L1tex queue, couples only
// 2 warps per __syncthreads. Body byte-identical to R10.

typedef unsigned long long u64;

static __device__ __forceinline__ u64 pk2(float a, float b) {
    u64 r; asm("mov.b64 %0, {%1, %2};" : "=l"(r) : "f"(a), "f"(b)); return r;
}
static __device__ __forceinline__ void upk2(u64 v, float& a, float& b) {
    asm("mov.b64 {%0, %1}, %2;" : "=f"(a), "=f"(b) : "l"(v));
}
static __device__ __forceinline__ u64 fma2(u64 a, u64 b, u64 c) {
    u64 d; asm("fma.rn.f32x2 %0, %1, %2, %3;" : "=l"(d) : "l"(a), "l"(b), "l"(c)); return d;
}
static __device__ __forceinline__ u64 add2(u64 a, u64 b) {
    u64 d; asm("add.rn.f32x2 %0, %1, %2;" : "=l"(d) : "l"(a), "l"(b)); return d;
}

__global__ void __launch_bounds__(64, 12) gnn_fused_kernel(
    const float* __restrict__ x,
    const float* __restrict__ z,
    const float* __restrict__ y,
    const float* __restrict__ enc_rel_w,
    const float* __restrict__ enc_rel_b,
    const float* __restrict__ enc_root_w,
    const float* __restrict__ pred_rel_w,
    const float* __restrict__ pred_rel_b,
    const float* __restrict__ pred_root_w,
    const float* __restrict__ dec_rel_w,
    const float* __restrict__ dec_rel_b,
    const float* __restrict__ dec_root_w,
    float* __restrict__ out,
    int NT)   // NT = 2*B threads
{
    __shared__ __align__(16) u64 sWRt2[32];  // [g*4+p]: enc_root_w^T packed over f
    __shared__ __align__(16) u64 sW2[64];    // [(fp*8+g)*2 + {0:wa,1:wb}]
    __shared__ __align__(16) u64 sEW2[4], sEB2[4], sPB2[4];
    __shared__ float sDW[8];
    __shared__ float sDB, sDR;

    const int tid = threadIdx.x;
    if (tid < 32) {
        {
            const int g = tid >> 2, p = tid & 3;
            sWRt2[g * 4 + p] = pk2(enc_root_w[(2*p)*8 + g], enc_root_w[(2*p + 1)*8 + g]);
        }
        {
            const int fp = tid >> 3, g = tid & 7;
            const float w = expf(-1.0f / 9.0f);
            float pr0 = pred_rel_w[(2*fp)*8 + g],   pr1 = pred_rel_w[(2*fp + 1)*8 + g];
            float po0 = pred_root_w[(2*fp)*8 + g],  po1 = pred_root_w[(2*fp + 1)*8 + g];
            sW2[(fp*8 + g)*2 + 0] = pk2(pr0 + po0, pr1 + po1);   // wa
            sW2[(fp*8 + g)*2 + 1] = pk2(w * pr0, w * pr1);       // wb
        }
        // second half of sW2 (fp = 2,3) handled by lanes 0..15 of warp 1 below
    }
    if (tid >= 32 && tid < 64) {
        const int q = tid - 32;              // 0..31 -> fp 2..3
        const int fp = 2 + (q >> 3) % 2, g = q & 7;
        if (q < 16) {
            const float w = expf(-1.0f / 9.0f);
            float pr0 = pred_rel_w[(2*fp)*8 + g],   pr1 = pred_rel_w[(2*fp + 1)*8 + g];
            float po0 = pred_root_w[(2*fp)*8 + g],  po1 = pred_root_w[(2*fp + 1)*8 + g];
            sW2[(fp*8 + g)*2 + 0] = pk2(pr0 + po0, pr1 + po1);
            sW2[(fp*8 + g)*2 + 1] = pk2(w * pr0, w * pr1);
        }
    }
    if (tid < 32) {
        // fp = 2,3 of sW2 also written here to be safe against blockDim < 64 tails
        const int fp = 2 + (tid >> 3);
        if (tid < 16) {
            const int g = tid & 7;
            const float w = expf(-1.0f / 9.0f);
            float pr0 = pred_rel_w[(2*fp)*8 + g],   pr1 = pred_rel_w[(2*fp + 1)*8 + g];
            float po0 = pred_root_w[(2*fp)*8 + g],  po1 = pred_root_w[(2*fp + 1)*8 + g];
            sW2[(fp*8 + g)*2 + 0] = pk2(pr0 + po0, pr1 + po1);
            sW2[(fp*8 + g)*2 + 1] = pk2(w * pr0, w * pr1);
        }
    }
    if (tid < 4) {
        sEW2[tid] = pk2(enc_rel_w[2*tid], enc_rel_w[2*tid + 1]);
        sEB2[tid] = pk2(enc_rel_b[2*tid], enc_rel_b[2*tid + 1]);
        sPB2[tid] = pk2(pred_rel_b[2*tid], pred_rel_b[2*tid + 1]);
    }
    if (tid < 8) sDW[tid] = dec_rel_w[tid];
    if (tid == 0) { sDB = dec_rel_b[0]; sDR = dec_root_w[0]; }
    __syncthreads();

    const int gt = blockIdx.x * blockDim.x + tid;
    if (gt >= NT) return;

    // ---------- coalesced front-batched loads (full MLP=15) ----------
    float4 c[5];
    {
        const float4* xp = reinterpret_cast<const float4*>(x) + gt * 5;
        #pragma unroll
        for (int i = 0; i < 5; i++) c[i] = xp[i];
    }
    float4 zl[10];
    {
        const float4* zp = reinterpret_cast<const float4*>(z) + gt * 10;
        #pragma unroll
        for (int i = 0; i < 10; i++) zl[i] = zp[i];
    }

    // ---------- s[5] straight from c[] ----------
    float s[5];
    {
        float m1 = __shfl_xor_sync(0xFFFFFFFFu, c[4].y, 1);
        float m2 = __shfl_xor_sync(0xFFFFFFFFu, c[4].z, 1);
        float m3 = __shfl_xor_sync(0xFFFFFFFFu, c[4].w, 1);
        s[0] = ((m1 + m2) + (m3 + c[0].x)) + (c[0].y + c[0].z);
        #pragma unroll
        for (int k = 1; k < 5; k++) {
            float a0 = c[k-1].y + c[k-1].z;
            float a1 = c[k-1].w + c[k].x;
            float a2 = c[k].y + c[k].z;
            s[k] = (a0 + a1) + a2;
        }
    }

    // ---------- encoder, k-outer: 4 packed accumulators per node ----------
    float z1[40];
    {
        const ulonglong2* EW = reinterpret_cast<const ulonglong2*>(sEW2);
        const ulonglong2* EB = reinterpret_cast<const ulonglong2*>(sEB2);
        const ulonglong2* WR = reinterpret_cast<const ulonglong2*>(sWRt2);
        ulonglong2 ew01 = EW[0], ew23 = EW[1];
        ulonglong2 eb01 = EB[0], eb23 = EB[1];
        #pragma unroll
        for (int k = 0; k < 5; k++) {
            float4 za = zl[2*k], zb = zl[2*k + 1];
            const float zv[8] = {za.x, za.y, za.z, za.w, zb.x, zb.y, zb.z, zb.w};
            u64 sk = pk2(s[k], s[k]);
            u64 A0 = fma2(sk, ew01.x, eb01.x);
            u64 A1 = fma2(sk, ew01.y, eb01.y);
            u64 A2 = fma2(sk, ew23.x, eb23.x);
            u64 A3 = fma2(sk, ew23.y, eb23.y);
            #pragma unroll
            for (int g = 0; g < 8; g++) {
                ulonglong2 w01 = WR[g*2];
                ulonglong2 w23 = WR[g*2 + 1];
                u64 zg = pk2(zv[g], zv[g]);
                A0 = fma2(zg, w01.x, A0);
                A1 = fma2(zg, w01.y, A1);
                A2 = fma2(zg, w23.x, A2);
                A3 = fma2(zg, w23.y, A3);
            }
            float a, b;
            upk2(A0, a, b); z1[k*8+0] = fmaxf(a, 0.f); z1[k*8+1] = fmaxf(b, 0.f);
            upk2(A1, a, b); z1[k*8+2] = fmaxf(a, 0.f); z1[k*8+3] = fmaxf(b, 0.f);
            upk2(A2, a, b); z1[k*8+4] = fmaxf(a, 0.f); z1[k*8+5] = fmaxf(b, 0.f);
            upk2(A3, a, b); z1[k*8+6] = fmaxf(a, 0.f); z1[k*8+7] = fmaxf(b, 0.f);
        }
    }

    // ---------- predictor + decoder-rel fused, (fp,g)-outer k-inner ----------
    float t[5] = {0.f, 0.f, 0.f, 0.f, 0.f};
    {
        const ulonglong2* W = reinterpret_cast<const ulonglong2*>(sW2);
        #pragma unroll
        for (int fp = 0; fp < 4; fp++) {
            u64 pb = sPB2[fp];
            u64 u2[5], v2[5];
            #pragma unroll
            for (int k = 0; k < 5; k++) { u2[k] = pb; v2[k] = 0ULL; }
            #pragma unroll
            for (int g = 0; g < 8; g++) {
                ulonglong2 w = W[fp*8 + g];   // {wa, wb}
                #pragma unroll
                for (int k = 0; k < 5; k++) {
                    u64 zg = pk2(z1[k*8 + g], z1[k*8 + g]);
                    u2[k] = fma2(zg, w.x, u2[k]);
                    v2[k] = fma2(zg, w.y, v2[k]);
                }
            }
            float va, vb;
            upk2(v2[4], va, vb);
            float vma = __shfl_xor_sync(0xFFFFFFFFu, va, 1);
            float vmb = __shfl_xor_sync(0xFFFFFFFFu, vb, 1);
            u64 vm2 = pk2(vma, vmb);
            upk2(v2[0], va, vb);
            float vpa = __shfl_xor_sync(0xFFFFFFFFu, va, 1);
            float vpb = __shfl_xor_sync(0xFFFFFFFFu, vb, 1);
            u64 vp2 = pk2(vpa, vpb);

            const float dw0 = sDW[2*fp], dw1 = sDW[2*fp + 1];
            #pragma unroll
            for (int k = 0; k < 5; k++) {
                u64 nb  = add2(k == 0 ? vm2 : v2[k-1], k == 4 ? vp2 : v2[k+1]);
                u64 pre = add2(u2[k], nb);
                float p0, p1; upk2(pre, p0, p1);
                t[k] = fmaf(fmaxf(p0, 0.0f), dw0, t[k]);
                t[k] = fmaf(fmaxf(p1, 0.0f), dw1, t[k]);
            }
        }
    }

    // ---------- decoder aggregation + root + output ----------
    float T6[6];
    #pragma unroll
    for (int k = 0; k < 5; k++) T6[k] = t[k];
    T6[5] = __shfl_xor_sync(0xFFFFFFFFu, t[0], 1);

    const float dB = sDB, dR = sDR;
    const float4* yp = reinterpret_cast<const float4*>(y) + gt * 5;
    float4* op = reinterpret_cast<float4*>(out) + gt * 5;
    #pragma unroll
    for (int q = 0; q < 5; q++) {
        float4 yv = yp[q];
        float yc[4] = {yv.x, yv.y, yv.z, yv.w};
        float r[4];
        #pragma unroll
        for (int cc = 0; cc < 4; cc++) {
            const int i = 4*q + cc;
            const int lo = (i + 1) / 4;
            const int hi = (i + 3) / 4;
            float agg = T6[lo];
            if (hi != lo) agg += T6[hi];
            r[cc] = fmaf(yc[cc], dR, agg + dB);
        }
        op[q] = make_float4(r[0], r[1], r[2], r[3]);
    }
}

extern "C" void kernel_launch(void* const* d_in, const int* in_sizes, int n_in,
                              void* d_out, int out_size) {
    const float* x           = (const float*)d_in[0];
    const float* z           = (const float*)d_in[1];
    const float* y           = (const float*)d_in[2];
    const float* enc_rel_w   = (const float*)d_in[3];
    const float* enc_rel_b   = (const float*)d_in[4];
    const float* enc_root_w  = (const float*)d_in[5];
    const float* pred_rel_w  = (const float*)d_in[6];
    const float* pred_rel_b  = (const float*)d_in[7];
    const float* pred_root_w = (const float*)d_in[8];
    const float* dec_rel_w   = (const float*)d_in[9];
    const float* dec_rel_b   = (const float*)d_in[10];
    const float* dec_root_w  = (const float*)d_in[11];
    float* out = (float*)d_out;

    const int B  = in_sizes[0] / 40;
    const int NT = 2 * B;
    const int threads = 64;
    const int blocks = (NT + threads - 1) / threads;
    gnn_fused_kernel<<<blocks, threads>>>(
        x, z, y, enc_rel_w, enc_rel_b, enc_root_w,
        pred_rel_w, pred_rel_b, pred_root_w,
        dec_rel_w, dec_rel_b, dec_root_w, out, NT);
}